// round 3
// baseline (speedup 1.0000x reference)
#include <cuda_runtime.h>
#include <cuda_fp16.h>
#include <cstdint>

#define CROP 8
#define W    512
#define CW   496
#define TX   16
#define TY   16
#define NT   256
#define SW   22
#define STAGEF (SW*SW*3)      /* 1452 floats per staged view tile */
#define PLANE  (W*W*3)        /* 786432 floats per view plane */
#define VALSH  (48*3*NT)      /* 36864 halves */
#define SMEM_BYTES (STAGEF*4 + VALSH*2 + 64)   /* 5808 + 73728 + 64 = 79600 */

__device__ double g_cl, g_gx, g_gy;

__global__ void k_init() { g_cl = 0.0; g_gx = 0.0; g_gy = 0.0; }

__device__ __forceinline__ int k_epoch(int e) {
  if (e < 200) return 0;
  if (e < 2300) return ((e - 200) / 100) * 2;
  return 44;
}

// ascending bitonic sort, fully unrolled
template <int N>
__device__ __forceinline__ void bsort(float (&a)[N]) {
#pragma unroll
  for (int k = 2; k <= N; k <<= 1) {
#pragma unroll
    for (int j = k >> 1; j > 0; j >>= 1) {
#pragma unroll
      for (int i = 0; i < N; i++) {
        int l = i ^ j;
        if (l > i) {
          float x = a[i], y = a[l];
          float lo = fminf(x, y), hi = fmaxf(x, y);
          bool up = ((i & k) == 0);
          a[i] = up ? lo : hi;
          a[l] = up ? hi : lo;
        }
      }
    }
  }
}

__global__ __launch_bounds__(NT, 2)
void k_main(const float* __restrict__ pred, const float* __restrict__ xin,
            const int* __restrict__ ep) {
  extern __shared__ float sm[];
  float*  stage = sm;                                   // STAGEF floats
  __half* vals  = (__half*)(sm + STAGEF);               // VALSH halves
  float*  red   = (float*)((char*)vals + VALSH * 2);    // 8 floats

  const int tid = threadIdx.x;
  const int lx = tid & 15, ly = tid >> 4;
  const int gx0 = CROP + blockIdx.x * TX;
  const int gy0 = CROP + blockIdx.y * TY;
  const int b = blockIdx.z;
  const int gx = gx0 + lx, gy = gy0 + ly;
  const float* xb = xin + (size_t)b * 49 * PLANE;
  const int row0 = gy0 - 3;
  const int col0f = (gx0 - 3) * 3;

  const float p = pred[((size_t)b * W + gy) * W + gx];
  const int epoch = ep ? ep[0] : 1000;
  const int K = 49 - k_epoch(epoch);

  float rbuf[6];
  // prefetch center view (24)
  {
    const float* pl = xb + (size_t)24 * PLANE + (size_t)row0 * (W * 3) + col0f;
#pragma unroll
    for (int k = 0; k < 6; k++) {
      int idx = tid + k * NT;
      if (idx < STAGEF) {
        int r = idx / 66, c = idx - r * 66;
        rbuf[k] = __ldg(pl + (size_t)r * (W * 3) + c);
      }
    }
  }

  float cen0 = 0.f, cen1 = 0.f, cen2 = 0.f;

  for (int i = 0; i < 49; i++) {
    __syncthreads();   // previous compute done before overwriting stage
#pragma unroll
    for (int k = 0; k < 6; k++) {
      int idx = tid + k * NT;
      if (idx < STAGEF) stage[idx] = rbuf[k];
    }
    __syncthreads();   // stage visible to all

    if (i < 48) {      // prefetch next view: s' = i -> n' = (i<24)? i : i+1
      int n2 = (i < 24) ? i : i + 1;
      const float* pl = xb + (size_t)n2 * PLANE + (size_t)row0 * (W * 3) + col0f;
#pragma unroll
      for (int k = 0; k < 6; k++) {
        int idx = tid + k * NT;
        if (idx < STAGEF) {
          int r = idx / 66, c = idx - r * 66;
          rbuf[k] = __ldg(pl + (size_t)r * (W * 3) + c);
        }
      }
    }

    if (i == 0) {
      int base = ((ly + 3) * SW + (lx + 3)) * 3;
      cen0 = stage[base]; cen1 = stage[base + 1]; cen2 = stage[base + 2];
    } else {
      int s = i - 1;
      int n = (s < 24) ? s : s + 1;
      float du = (float)(n / 7 - 3);
      float dv = (float)(n % 7 - 3);
      float ty = (float)gy + p * du;
      float tx = (float)gx + p * dv;
      float fy = floorf(ty), fx = floorf(tx);
      float wy = ty - fy, wx = tx - fx;
      int iy = (int)fy - row0;
      int ix = (int)fx - (gx0 - 3);
      int base = (iy * SW + ix) * 3;
      float v00, v01, v10, v11, a0, a1, rr;

      v00 = stage[base];      v01 = stage[base + 3];
      v10 = stage[base + 66]; v11 = stage[base + 69];
      a0 = v00 + wx * (v01 - v00); a1 = v10 + wx * (v11 - v10);
      rr = a0 + wy * (a1 - a0);
      vals[(s * 3 + 0) * NT + tid] = __float2half_rn(fabsf(rr - cen0));

      v00 = stage[base + 1];  v01 = stage[base + 4];
      v10 = stage[base + 67]; v11 = stage[base + 70];
      a0 = v00 + wx * (v01 - v00); a1 = v10 + wx * (v11 - v10);
      rr = a0 + wy * (a1 - a0);
      vals[(s * 3 + 1) * NT + tid] = __float2half_rn(fabsf(rr - cen1));

      v00 = stage[base + 2];  v01 = stage[base + 5];
      v10 = stage[base + 68]; v11 = stage[base + 71];
      a0 = v00 + wx * (v01 - v00); a1 = v10 + wx * (v11 - v10);
      rr = a0 + wy * (a1 - a0);
      vals[(s * 3 + 2) * NT + tid] = __float2half_rn(fabsf(rr - cen2));
    }
  }

  // ---------------- phase 2: per-channel rank select + masked sum ----------
  // Each thread reads only its own vals lane: no sync needed.
  float mysum = 0.f;
  if (K == 33) {
#pragma unroll
    for (int c = 0; c < 3; c++) {
      float A[32], B[16];
#pragma unroll
      for (int s = 0; s < 32; s++) A[s] = __half2float(vals[(s * 3 + c) * NT + tid]);
#pragma unroll
      for (int s = 0; s < 16; s++) B[s] = __half2float(vals[((32 + s) * 3 + c) * NT + tid]);
      bsort<32>(A);
      bsort<16>(B);
      // rank-32 (1-indexed) of A(32) U B(16)
      float t = A[31];
#pragma unroll
      for (int i2 = 16; i2 <= 31; i2++) t = fminf(t, fmaxf(A[i2 - 1], B[31 - i2]));
      float s0 = 0.f;
#pragma unroll
      for (int s = 0; s < 32; s++) s0 += (A[s] <= t) ? A[s] : 0.f;
#pragma unroll
      for (int s = 0; s < 16; s++) s0 += (B[s] <= t) ? B[s] : 0.f;
      mysum += s0;
    }
  } else {
    // generic rank r = K-1 among the 48 non-center values (never taken @epoch 1000)
    int r = K - 1;
    for (int c = 0; c < 3; c++) {
      float t = 3.0e38f;
      for (int a = 0; a < 48; a++) {
        float va = __half2float(vals[(a * 3 + c) * NT + tid]);
        int cnt = 0;
        for (int q = 0; q < 48; q++)
          cnt += (__half2float(vals[(q * 3 + c) * NT + tid]) <= va) ? 1 : 0;
        if (cnt >= r) t = fminf(t, va);
      }
      float s0 = 0.f;
      for (int a = 0; a < 48; a++) {
        float va = __half2float(vals[(a * 3 + c) * NT + tid]);
        s0 += (va <= t) ? va : 0.f;
      }
      mysum += s0;
    }
  }

  // block reduce -> one double atomic
#pragma unroll
  for (int o = 16; o > 0; o >>= 1) mysum += __shfl_down_sync(0xffffffffu, mysum, o);
  if ((tid & 31) == 0) red[tid >> 5] = mysum;
  __syncthreads();
  if (tid == 0) {
    float tot = 0.f;
    for (int w2 = 0; w2 < NT / 32; w2++) tot += red[w2];
    atomicAdd(&g_cl, (double)tot);
  }
}

// ---------------- edge-aware smoothness ----------------
__global__ void k_grad(const float* __restrict__ pred, const float* __restrict__ xin) {
  int idx = blockIdx.x * 256 + threadIdx.x;
  float sx = 0.f, sy = 0.f;
  if (idx < 2 * CW * CW) {
    int b = idx / (CW * CW);
    int rem = idx - b * (CW * CW);
    int y = CROP + rem / CW;
    int x = CROP + rem % CW;
    const float* I = xin + ((size_t)b * 49 + 24) * PLANE;
    const float* D = pred + (size_t)b * W * W;
    size_t o = (size_t)y * W + x;
    float i0 = I[o * 3], i1 = I[o * 3 + 1], i2 = I[o * 3 + 2];
    float d0 = D[o];
    if (x < CROP + CW - 1) {  // gx valid: x in [8,502], y in [8,503]
      float a = fabsf(I[(o + 1) * 3] - i0) + fabsf(I[(o + 1) * 3 + 1] - i1) +
                fabsf(I[(o + 1) * 3 + 2] - i2);
      sx = expf(-50.f * a) * fabsf(D[o + 1] - d0);
    }
    if (y < CROP + CW - 1) {  // gy valid: y in [8,502], x in [8,503]
      float a = fabsf(I[(o + W) * 3] - i0) + fabsf(I[(o + W) * 3 + 1] - i1) +
                fabsf(I[(o + W) * 3 + 2] - i2);
      sy = expf(-50.f * a) * fabsf(D[o + W] - d0);
    }
  }
#pragma unroll
  for (int o2 = 16; o2 > 0; o2 >>= 1) {
    sx += __shfl_down_sync(0xffffffffu, sx, o2);
    sy += __shfl_down_sync(0xffffffffu, sy, o2);
  }
  __shared__ float rx[8], ry[8];
  int tid = threadIdx.x;
  if ((tid & 31) == 0) { rx[tid >> 5] = sx; ry[tid >> 5] = sy; }
  __syncthreads();
  if (tid == 0) {
    float a = 0.f, c = 0.f;
    for (int w2 = 0; w2 < 8; w2++) { a += rx[w2]; c += ry[w2]; }
    atomicAdd(&g_gx, (double)a);
    atomicAdd(&g_gy, (double)c);
  }
}

__global__ void k_fin(const int* __restrict__ ep, float* __restrict__ out) {
  int epoch = ep ? ep[0] : 1000;
  int K = 49 - k_epoch(epoch);
  // mean(cl) = g_cl * (49/K) / (2*3*49*496*496) = g_cl / (K * 6 * 496^2)
  double mcl = g_cl / ((double)K * 6.0 * 496.0 * 496.0);
  double den = 2.0 * 496.0 * 495.0;   // identical count for lx and ly
  double gl = 0.5 * (g_gx / den + g_gy / den);
  out[0] = (float)(mcl + 0.1 * gl);
}

extern "C" void kernel_launch(void* const* d_in, const int* in_sizes, int n_in,
                              void* d_out, int out_size) {
  const float* pred = (const float*)d_in[0];
  const float* x    = (const float*)d_in[1];
  const int*   ep   = (n_in >= 3) ? (const int*)d_in[2] : nullptr;

  cudaFuncSetAttribute(k_main, cudaFuncAttributeMaxDynamicSharedMemorySize, SMEM_BYTES);

  k_init<<<1, 1>>>();
  dim3 grid(31, 31, 2);
  k_main<<<grid, NT, SMEM_BYTES>>>(pred, x, ep);
  k_grad<<<(2 * CW * CW + 255) / 256, 256>>>(pred, x);
  k_fin<<<1, 1>>>(ep, (float*)d_out);
}

// round 4
// speedup vs baseline: 1.2840x; 1.2840x over previous
#include <cuda_runtime.h>
#include <cstdint>

#define CROP 8
#define W    512
#define CW   496
#define TX   16
#define TY   16
#define NPIX 256
#define NT   768               /* 256 pixels x 3 channels */
#define SW   22
#define STAGEF (SW*SW*3)       /* 1452 floats per view tile */
#define PLANE  (W*W*3)
#define VALS_OFF (2*STAGEF)                      /* floats */
#define RED_OFF  (VALS_OFF + 48*NT)              /* floats */
#define SMEM_FLOATS (RED_OFF + 32)
#define SMEM_BYTES (SMEM_FLOATS*4)               /* ~159.4 KB */

__device__ double g_cl, g_gx, g_gy;

__global__ void k_init() { g_cl = 0.0; g_gx = 0.0; g_gy = 0.0; }

__device__ __forceinline__ int k_epoch(int e) {
  if (e < 200) return 0;
  if (e < 2300) return ((e - 200) / 100) * 2;
  return 44;
}

// ascending bitonic sort, fully unrolled (proven in round 3)
template <int N>
__device__ __forceinline__ void bsort(float (&a)[N]) {
#pragma unroll
  for (int k = 2; k <= N; k <<= 1) {
#pragma unroll
    for (int j = k >> 1; j > 0; j >>= 1) {
#pragma unroll
      for (int i = 0; i < N; i++) {
        int l = i ^ j;
        if (l > i) {
          float x = a[i], y = a[l];
          float lo = fminf(x, y), hi = fmaxf(x, y);
          bool up = ((i & k) == 0);
          a[i] = up ? lo : hi;
          a[l] = up ? hi : lo;
        }
      }
    }
  }
}

// bilinear sample of channel ch at (ty,tx) from a staged tile, minus center
__device__ __forceinline__ float bilin_diff(const float* __restrict__ stg,
                                            float ty, float tx,
                                            int row0, int col0, int ch, float cen) {
  float fy = floorf(ty), fx = floorf(tx);
  float wy = ty - fy, wx = tx - fx;
  int iy = (int)fy - row0;
  int ix = (int)fx - col0;
  int base = (iy * SW + ix) * 3 + ch;
  float v00 = stg[base],      v01 = stg[base + 3];
  float v10 = stg[base + 66], v11 = stg[base + 69];
  float a0 = v00 + wx * (v01 - v00);
  float a1 = v10 + wx * (v11 - v10);
  float r  = a0 + wy * (a1 - a0);
  return fabsf(r - cen);
}

__global__ __launch_bounds__(NT, 1)
void k_main(const float* __restrict__ pred, const float* __restrict__ xin,
            const int* __restrict__ ep) {
  extern __shared__ float sm[];
  float* stage = sm;                 // 2 tiles: stage[v*STAGEF + idx]
  float* vals  = sm + VALS_OFF;      // vals[s*NT + tid], fp32
  float* red   = sm + RED_OFF;

  const int tid = threadIdx.x;
  const int ch  = tid >> 8;          // 0..2
  const int pix = tid & 255;
  const int lx = pix & 15, ly = pix >> 4;
  const int gx0 = CROP + blockIdx.x * TX;
  const int gy0 = CROP + blockIdx.y * TY;
  const int b = blockIdx.z;
  const int gx = gx0 + lx, gy = gy0 + ly;
  const int row0 = gy0 - 3, col0 = gx0 - 3;
  const float* xb = xin + (size_t)b * 49 * PLANE;

  const float p = __ldg(pred + ((size_t)b * W + gy) * W + gx);
  const float fgy = (float)gy, fgx = (float)gx;
  const int epoch = ep ? ep[0] : 1000;
  const int K = 49 - k_epoch(epoch);

  // per-thread staging offsets (idx = tid, tid+768): loop-invariant
  int sidx0 = tid, sidx1 = tid + NT;
  int r0 = sidx0 / 66, c0 = sidx0 - r0 * 66;
  int r1 = sidx1 / 66, c1 = sidx1 - r1 * 66;
  size_t goff0 = (size_t)(row0 + r0) * (W * 3) + (size_t)col0 * 3 + c0;
  size_t goff1 = (size_t)(row0 + r1) * (W * 3) + (size_t)col0 * 3 + c1;
  const bool ok1 = (sidx1 < STAGEF);   // 768..1451 valid, rest not

  // ---- stage center view (24) into stage[0] ----
  {
    const float* pl = xb + (size_t)24 * PLANE;
    stage[sidx0] = __ldg(pl + goff0);
    if (ok1) stage[sidx1] = __ldg(pl + goff1);
  }
  __syncthreads();
  const float cen = stage[((ly + 3) * SW + (lx + 3)) * 3 + ch];

  // ---- prefetch pair 0 (views s=0,1 -> n=0,1) ----
  float rb0, rb1, rb2, rb3;
  {
    const float* pl0 = xb;                       // n=0
    const float* pl1 = xb + (size_t)1 * PLANE;   // n=1
    rb0 = __ldg(pl0 + goff0);
    rb1 = ok1 ? __ldg(pl0 + goff1) : 0.f;
    rb2 = __ldg(pl1 + goff0);
    rb3 = ok1 ? __ldg(pl1 + goff1) : 0.f;
  }

  for (int j = 0; j < 24; j++) {
    __syncthreads();                 // prior reads of stage complete
    stage[sidx0] = rb0;
    if (ok1) stage[sidx1] = rb1;
    stage[STAGEF + sidx0] = rb2;
    if (ok1) stage[STAGEF + sidx1] = rb3;
    __syncthreads();                 // staged pair visible

    if (j < 23) {                    // prefetch pair j+1
      int s0n = 2 * (j + 1);
      int n0 = (s0n < 24) ? s0n : s0n + 1;
      int n1 = (s0n + 1 < 24) ? s0n + 1 : s0n + 2;
      const float* pl0 = xb + (size_t)n0 * PLANE;
      const float* pl1 = xb + (size_t)n1 * PLANE;
      rb0 = __ldg(pl0 + goff0);
      rb1 = ok1 ? __ldg(pl0 + goff1) : 0.f;
      rb2 = __ldg(pl1 + goff0);
      rb3 = ok1 ? __ldg(pl1 + goff1) : 0.f;
    }

    // compute views s=2j, 2j+1
    {
      int s = 2 * j;
      int n = (s < 24) ? s : s + 1;
      float du = (float)(n / 7 - 3), dv = (float)(n % 7 - 3);
      float ty = __fadd_rn(fgy, __fmul_rn(p, du));
      float tx = __fadd_rn(fgx, __fmul_rn(p, dv));
      vals[s * NT + tid] = bilin_diff(stage, ty, tx, row0, col0, ch, cen);
    }
    {
      int s = 2 * j + 1;
      int n = (s < 24) ? s : s + 1;
      float du = (float)(n / 7 - 3), dv = (float)(n % 7 - 3);
      float ty = __fadd_rn(fgy, __fmul_rn(p, du));
      float tx = __fadd_rn(fgx, __fmul_rn(p, dv));
      vals[s * NT + tid] = bilin_diff(stage + STAGEF, ty, tx, row0, col0, ch, cen);
    }
  }

  // ---------------- phase 2: rank select + masked sum (one channel/thread) ---
  float mysum = 0.f;
  if (K == 33) {
    float A[32], B[16];
#pragma unroll
    for (int s = 0; s < 32; s++) A[s] = vals[s * NT + tid];
#pragma unroll
    for (int s = 0; s < 16; s++) B[s] = vals[(32 + s) * NT + tid];
    bsort<32>(A);
    bsort<16>(B);
    // t = rank-32 (1-indexed) of A(32) U B(16): min over i+j=32 of max(A_i,B_j)
    float t = A[31];
#pragma unroll
    for (int i2 = 16; i2 <= 31; i2++) t = fminf(t, fmaxf(A[i2 - 1], B[31 - i2]));
    // >=16 elements of A are <= t guaranteed: sum A[0..15] unconditionally
    float s0 = 0.f, s1 = 0.f;
#pragma unroll
    for (int s = 0; s < 16; s++) { s0 += A[s]; s1 += A[16 + s] <= t ? A[16 + s] : 0.f; }
#pragma unroll
    for (int s = 0; s < 16; s++) s1 += (B[s] <= t) ? B[s] : 0.f;
    mysum = s0 + s1;
  } else {
    // generic rank r = K-1 among 48 non-center values (not taken @epoch 1000)
    int r = K - 1;
    float t = 3.0e38f;
    for (int a = 0; a < 48; a++) {
      float va = vals[a * NT + tid];
      int cnt = 0;
      for (int q = 0; q < 48; q++) cnt += (vals[q * NT + tid] <= va) ? 1 : 0;
      if (cnt >= r) t = fminf(t, va);
    }
    for (int a = 0; a < 48; a++) {
      float va = vals[a * NT + tid];
      mysum += (va <= t) ? va : 0.f;
    }
  }

  // block reduce -> one double atomic
#pragma unroll
  for (int o = 16; o > 0; o >>= 1) mysum += __shfl_down_sync(0xffffffffu, mysum, o);
  if ((tid & 31) == 0) red[tid >> 5] = mysum;
  __syncthreads();
  if (tid == 0) {
    float tot = 0.f;
    for (int w2 = 0; w2 < NT / 32; w2++) tot += red[w2];
    atomicAdd(&g_cl, (double)tot);
  }
}

// ---------------- edge-aware smoothness ----------------
__global__ void k_grad(const float* __restrict__ pred, const float* __restrict__ xin) {
  int idx = blockIdx.x * 256 + threadIdx.x;
  float sx = 0.f, sy = 0.f;
  if (idx < 2 * CW * CW) {
    int b = idx / (CW * CW);
    int rem = idx - b * (CW * CW);
    int y = CROP + rem / CW;
    int x = CROP + rem % CW;
    const float* I = xin + ((size_t)b * 49 + 24) * PLANE;
    const float* D = pred + (size_t)b * W * W;
    size_t o = (size_t)y * W + x;
    float i0 = I[o * 3], i1 = I[o * 3 + 1], i2 = I[o * 3 + 2];
    float d0 = D[o];
    if (x < CROP + CW - 1) {
      float a = fabsf(I[(o + 1) * 3] - i0) + fabsf(I[(o + 1) * 3 + 1] - i1) +
                fabsf(I[(o + 1) * 3 + 2] - i2);
      sx = expf(-50.f * a) * fabsf(D[o + 1] - d0);
    }
    if (y < CROP + CW - 1) {
      float a = fabsf(I[(o + W) * 3] - i0) + fabsf(I[(o + W) * 3 + 1] - i1) +
                fabsf(I[(o + W) * 3 + 2] - i2);
      sy = expf(-50.f * a) * fabsf(D[o + W] - d0);
    }
  }
#pragma unroll
  for (int o2 = 16; o2 > 0; o2 >>= 1) {
    sx += __shfl_down_sync(0xffffffffu, sx, o2);
    sy += __shfl_down_sync(0xffffffffu, sy, o2);
  }
  __shared__ float rx[8], ry[8];
  int tid = threadIdx.x;
  if ((tid & 31) == 0) { rx[tid >> 5] = sx; ry[tid >> 5] = sy; }
  __syncthreads();
  if (tid == 0) {
    float a = 0.f, c = 0.f;
    for (int w2 = 0; w2 < 8; w2++) { a += rx[w2]; c += ry[w2]; }
    atomicAdd(&g_gx, (double)a);
    atomicAdd(&g_gy, (double)c);
  }
}

__global__ void k_fin(const int* __restrict__ ep, float* __restrict__ out) {
  int epoch = ep ? ep[0] : 1000;
  int K = 49 - k_epoch(epoch);
  double mcl = g_cl / ((double)K * 6.0 * 496.0 * 496.0);
  double den = 2.0 * 496.0 * 495.0;
  double gl = 0.5 * (g_gx / den + g_gy / den);
  out[0] = (float)(mcl + 0.1 * gl);
}

extern "C" void kernel_launch(void* const* d_in, const int* in_sizes, int n_in,
                              void* d_out, int out_size) {
  const float* pred = (const float*)d_in[0];
  const float* x    = (const float*)d_in[1];
  const int*   ep   = (n_in >= 3) ? (const int*)d_in[2] : nullptr;

  cudaFuncSetAttribute(k_main, cudaFuncAttributeMaxDynamicSharedMemorySize, SMEM_BYTES);

  k_init<<<1, 1>>>();
  dim3 grid(31, 31, 2);
  k_main<<<grid, NT, SMEM_BYTES>>>(pred, x, ep);
  k_grad<<<(2 * CW * CW + 255) / 256, 256>>>(pred, x);
  k_fin<<<1, 1>>>(ep, (float*)d_out);
}